// round 2
// baseline (speedup 1.0000x reference)
#include <cuda_runtime.h>
#include <cuda_bf16.h>

#define N_NODES 50000
#define N_EDGES 800000
#define DIM 64
#define NB_SCAN 49   // ceil(50000/1024)

// Scratch (device globals — no allocation allowed)
__device__ int   g_deg[N_NODES];
__device__ int   g_row[N_NODES];
__device__ int   g_cur[N_NODES];
__device__ int   g_col[N_EDGES];
__device__ int   g_bsum[64];
__device__ int   g_boff[64];
__device__ float g_x1[N_NODES * DIM];
__device__ float g_agg[N_NODES * DIM];

// ---------------------------------------------------------------- CSR build
__global__ void k_zero_deg() {
    int i = blockIdx.x * blockDim.x + threadIdx.x;
    if (i < N_NODES) g_deg[i] = 0;
}

__global__ void k_hist(const int* __restrict__ ei) {
    int e = blockIdx.x * blockDim.x + threadIdx.x;
    if (e < N_EDGES) atomicAdd(&g_deg[ei[N_EDGES + e]], 1);
}

__global__ void k_scan1() {
    __shared__ int s[1024];
    int t = threadIdx.x;
    int i = blockIdx.x * 1024 + t;
    int v = (i < N_NODES) ? g_deg[i] : 0;
    s[t] = v;
    __syncthreads();
    #pragma unroll
    for (int off = 1; off < 1024; off <<= 1) {
        int tmp = (t >= off) ? s[t - off] : 0;
        __syncthreads();
        s[t] += tmp;
        __syncthreads();
    }
    if (i < N_NODES) g_row[i] = s[t] - v;   // exclusive within block
    if (t == 1023) g_bsum[blockIdx.x] = s[1023];
}

__global__ void k_scan2() {
    int run = 0;
    for (int b = 0; b < NB_SCAN; b++) {
        g_boff[b] = run;
        run += g_bsum[b];
    }
}

__global__ void k_scan3() {
    int i = blockIdx.x * 1024 + threadIdx.x;
    if (i < N_NODES) {
        int r = g_row[i] + g_boff[blockIdx.x];
        g_row[i] = r;
        g_cur[i] = r;
    }
}

__global__ void k_scatter(const int* __restrict__ ei) {
    int e = blockIdx.x * blockDim.x + threadIdx.x;
    if (e < N_EDGES) {
        int d = ei[N_EDGES + e];
        int p = atomicAdd(&g_cur[d], 1);
        g_col[p] = ei[e];
    }
}

// ------------------------------------------------------------- aggregation
// One warp per node: mean over {self} ∪ in-neighbors, written to g_agg.
__global__ void k_agg(const float* __restrict__ x) {
    int w    = (blockIdx.x * blockDim.x + threadIdx.x) >> 5;
    int lane = threadIdx.x & 31;
    if (w >= N_NODES) return;

    const float2* xs = (const float2*)x;
    float2 v = xs[w * 32 + lane];
    float a0 = v.x, a1 = v.y;

    int start = g_row[w];
    int cnt   = g_deg[w];

    for (int base = 0; base < cnt; base += 32) {
        int rem = cnt - base;
        int m   = rem < 32 ? rem : 32;
        int c   = (lane < m) ? g_col[start + base + lane] : 0;
        int t = 0;
        for (; t + 4 <= m; t += 4) {
            int s0 = __shfl_sync(0xffffffffu, c, t);
            int s1 = __shfl_sync(0xffffffffu, c, t + 1);
            int s2 = __shfl_sync(0xffffffffu, c, t + 2);
            int s3 = __shfl_sync(0xffffffffu, c, t + 3);
            float2 v0 = xs[s0 * 32 + lane];
            float2 v1 = xs[s1 * 32 + lane];
            float2 v2 = xs[s2 * 32 + lane];
            float2 v3 = xs[s3 * 32 + lane];
            a0 += v0.x; a1 += v0.y;
            a0 += v1.x; a1 += v1.y;
            a0 += v2.x; a1 += v2.y;
            a0 += v3.x; a1 += v3.y;
        }
        for (; t < m; t++) {
            int s = __shfl_sync(0xffffffffu, c, t);
            float2 vv = xs[s * 32 + lane];
            a0 += vv.x; a1 += vv.y;
        }
    }
    float inv = 1.0f / (float)(cnt + 1);
    ((float2*)g_agg)[w * 32 + lane] = make_float2(a0 * inv, a1 * inv);
}

// ------------------------------------------------------------------- GEMM
// out[n] = relu( agg[n] @ Wl + bl + x[n] @ Wr )
// Block: 256 threads, 128 nodes. Weights in shared, k-major staged inputs.
__global__ void __launch_bounds__(256) k_mm(const float* __restrict__ x,
                                            const float* __restrict__ Wl,
                                            const float* __restrict__ bl,
                                            const float* __restrict__ Wr,
                                            float* __restrict__ out) {
    __shared__ float wl_s[DIM * DIM];
    __shared__ float wr_s[DIM * DIM];
    __shared__ float a_s[8][128];
    __shared__ float x_s[8][128];

    int tid = threadIdx.x;
    for (int i = tid; i < DIM * DIM / 4; i += 256) {
        ((float4*)wl_s)[i] = ((const float4*)Wl)[i];
        ((float4*)wr_s)[i] = ((const float4*)Wr)[i];
    }

    int node0 = blockIdx.x * 128;
    int nrow  = (tid >> 3) << 2;   // 0,4,...,124
    int fcol  = (tid & 7) << 3;    // 0,8,...,56

    float acc[4][8];
    #pragma unroll
    for (int i = 0; i < 4; i++)
        #pragma unroll
        for (int f = 0; f < 8; f++) acc[i][f] = 0.f;

    int nl = tid >> 1;
    int k4 = (tid & 1) * 4;

    for (int kc = 0; kc < 8; kc++) {
        int k0 = kc * 8;
        __syncthreads();   // protect previous chunk reads (and weight loads on kc=0)
        {
            int node = node0 + nl;
            float4 vx = make_float4(0.f, 0.f, 0.f, 0.f), va = vx;
            if (node < N_NODES) {
                vx = *(const float4*)(x     + node * DIM + k0 + k4);
                va = *(const float4*)(g_agg + node * DIM + k0 + k4);
            }
            x_s[k4 + 0][nl] = vx.x; x_s[k4 + 1][nl] = vx.y;
            x_s[k4 + 2][nl] = vx.z; x_s[k4 + 3][nl] = vx.w;
            a_s[k4 + 0][nl] = va.x; a_s[k4 + 1][nl] = va.y;
            a_s[k4 + 2][nl] = va.z; a_s[k4 + 3][nl] = va.w;
        }
        __syncthreads();

        #pragma unroll
        for (int kk = 0; kk < 8; kk++) {
            float wlv[8], wrv[8];
            *(float4*)&wlv[0] = *(const float4*)&wl_s[(k0 + kk) * DIM + fcol];
            *(float4*)&wlv[4] = *(const float4*)&wl_s[(k0 + kk) * DIM + fcol + 4];
            *(float4*)&wrv[0] = *(const float4*)&wr_s[(k0 + kk) * DIM + fcol];
            *(float4*)&wrv[4] = *(const float4*)&wr_s[(k0 + kk) * DIM + fcol + 4];
            #pragma unroll
            for (int i = 0; i < 4; i++) {
                float av = a_s[kk][nrow + i];
                float xv = x_s[kk][nrow + i];
                #pragma unroll
                for (int f = 0; f < 8; f++)
                    acc[i][f] += av * wlv[f] + xv * wrv[f];
            }
        }
    }

    float bv[8];
    *(float4*)&bv[0] = *(const float4*)(bl + fcol);
    *(float4*)&bv[4] = *(const float4*)(bl + fcol + 4);

    #pragma unroll
    for (int i = 0; i < 4; i++) {
        int node = node0 + nrow + i;
        if (node < N_NODES) {
            float4 o0, o1;
            o0.x = fmaxf(acc[i][0] + bv[0], 0.f);
            o0.y = fmaxf(acc[i][1] + bv[1], 0.f);
            o0.z = fmaxf(acc[i][2] + bv[2], 0.f);
            o0.w = fmaxf(acc[i][3] + bv[3], 0.f);
            o1.x = fmaxf(acc[i][4] + bv[4], 0.f);
            o1.y = fmaxf(acc[i][5] + bv[5], 0.f);
            o1.z = fmaxf(acc[i][6] + bv[6], 0.f);
            o1.w = fmaxf(acc[i][7] + bv[7], 0.f);
            *(float4*)(out + node * DIM + fcol)     = o0;
            *(float4*)(out + node * DIM + fcol + 4) = o1;
        }
    }
}

// ------------------------------------------------------------------ launch
extern "C" void kernel_launch(void* const* d_in, const int* in_sizes, int n_in,
                              void* d_out, int out_size) {
    const float* x    = (const float*)d_in[0];
    const int*   ei   = (const int*)  d_in[1];
    const float* Wl0  = (const float*)d_in[2];
    const float* bl0  = (const float*)d_in[3];
    const float* Wr0  = (const float*)d_in[4];
    const float* Wl1  = (const float*)d_in[5];
    const float* bl1  = (const float*)d_in[6];
    const float* Wr1  = (const float*)d_in[7];
    float* out = (float*)d_out;

    // CSR build (edges identical for both layers)
    k_zero_deg<<<(N_NODES + 255) / 256, 256>>>();
    k_hist<<<(N_EDGES + 255) / 256, 256>>>(ei);
    k_scan1<<<NB_SCAN, 1024>>>();
    k_scan2<<<1, 1>>>();
    k_scan3<<<NB_SCAN, 1024>>>();
    k_scatter<<<(N_EDGES + 255) / 256, 256>>>(ei);

    int agg_blocks = (N_NODES * 32 + 255) / 256;
    int mm_blocks  = (N_NODES + 127) / 128;

    // Layer 0
    k_agg<<<agg_blocks, 256>>>(x);
    k_mm<<<mm_blocks, 256>>>(x, Wl0, bl0, Wr0, g_x1);
    // Layer 1
    k_agg<<<agg_blocks, 256>>>(g_x1);
    k_mm<<<mm_blocks, 256>>>(g_x1, Wl1, bl1, Wr1, out);
}